// round 1
// baseline (speedup 1.0000x reference)
#include <cuda_runtime.h>
#include <cstdint>

#define NBOX     262144
#define ROWLEN   85
#define NCLS     80
#define NBUCKET  16384
#define MAXSEL   300
#define CHUNK    256
#define NWORDS   (CHUNK / 32)

// ---------------- device scratch (no allocations allowed) ----------------
__device__ uint32_t            g_hist[NBUCKET];
__device__ uint32_t            g_base[NBUCKET];
__device__ uint32_t            g_cursor[NBUCKET];
__device__ uint32_t            g_count;
__device__ unsigned long long  g_ucand[NBOX];
__device__ unsigned long long  g_sorted[NBOX];

// ---------------- exact IoU > 0.5 decision (match XLA association) -------
__device__ __forceinline__ bool iou_gt(float4 a, float4 b) {
    // fields: x=y1, y=x1, z=y2, w=x2
    float y1 = fmaxf(a.x, b.x);
    float x1 = fmaxf(a.y, b.y);
    float y2 = fminf(a.z, b.z);
    float x2 = fminf(a.w, b.w);
    float ih = fmaxf(__fsub_rn(y2, y1), 0.0f);
    float iw = fmaxf(__fsub_rn(x2, x1), 0.0f);
    float inter = __fmul_rn(ih, iw);
    float aa = __fmul_rn(fmaxf(__fsub_rn(a.z, a.x), 0.0f),
                         fmaxf(__fsub_rn(a.w, a.y), 0.0f));
    float ab = __fmul_rn(fmaxf(__fsub_rn(b.z, b.x), 0.0f),
                         fmaxf(__fsub_rn(b.w, b.y), 0.0f));
    // area_a + area_b - inter + 1e-9 with left-assoc order
    float denom = __fadd_rn(__fsub_rn(__fadd_rn(aa, ab), inter), 1e-9f);
    return __fdiv_rn(inter, denom) > 0.5f;
}

// ---------------- P0: init ----------------
__global__ void init_kernel() {
    int i = blockIdx.x * blockDim.x + threadIdx.x;
    if (i < NBUCKET) g_hist[i] = 0;
    if (i == 0) g_count = 0;
}

// ---------------- P1: score / class / threshold / compact + histogram ----
__global__ void score_kernel(const float* __restrict__ in) {
    int warp = (blockIdx.x * blockDim.x + threadIdx.x) >> 5;
    int lane = threadIdx.x & 31;
    if (warp >= NBOX) return;
    const float* row = in + (size_t)warp * ROWLEN;

    float conf = __ldg(row + 4);   // broadcast load (same addr across warp)

    float best = -1.0f;
    int   bcls = 127;

    // lane handles classes (lane-5), (lane+27), (lane+59) — ascending order,
    // strict '>' keeps the FIRST max (matches jnp.argmax tie-break).
    if (lane >= 5) {
        float s = __fmul_rn(conf, __ldg(row + lane));          // class lane-5
        if (s > best) { best = s; bcls = lane - 5; }
    }
    {
        float s = __fmul_rn(conf, __ldg(row + 32 + lane));     // class lane+27
        if (s > best) { best = s; bcls = lane + 27; }
    }
    if (lane < 21) {
        float s = __fmul_rn(conf, __ldg(row + 64 + lane));     // class lane+59
        if (s > best) { best = s; bcls = lane + 59; }
    }

    // warp argmax reduce: larger score wins; equal score -> smaller class
    #pragma unroll
    for (int off = 16; off; off >>= 1) {
        float ob = __shfl_down_sync(0xFFFFFFFFu, best, off);
        int   oc = __shfl_down_sync(0xFFFFFFFFu, bcls, off);
        if (ob > best || (ob == best && oc < bcls)) { best = ob; bcls = oc; }
    }

    if (lane == 0 && best >= 0.6f) {
        uint32_t sb = __float_as_uint(best);                   // positive -> monotone bits
        atomicAdd(&g_hist[(sb >> 9) & (NBUCKET - 1)], 1u);     // top-14 mantissa bits
        uint32_t pos = atomicAdd(&g_count, 1u);
        unsigned long long key =
            ((unsigned long long)sb << 25) |
            ((unsigned long long)(NBOX - 1 - warp) << 7) |     // desc key -> asc idx on ties
            (unsigned long long)bcls;
        g_ucand[pos] = key;
    }
}

// ---------------- P2: descending-order exclusive scan of histogram -------
__global__ void scan_kernel() {
    __shared__ uint32_t ssum[1024];
    int t = threadIdx.x;
    const int PER = NBUCKET / 1024;   // 16
    uint32_t cnt[PER];
    uint32_t local = 0;
    #pragma unroll
    for (int k = 0; k < PER; k++) {
        int b = NBUCKET - 1 - (t * PER + k);   // walk buckets descending
        cnt[k] = g_hist[b];
        local += cnt[k];
    }
    ssum[t] = local;
    __syncthreads();
    for (int off = 1; off < 1024; off <<= 1) {
        uint32_t y = 0;
        if (t >= off) y = ssum[t - off];
        __syncthreads();
        if (t >= off) ssum[t] += y;
        __syncthreads();
    }
    uint32_t run = ssum[t] - local;    // exclusive prefix (descending order)
    #pragma unroll
    for (int k = 0; k < PER; k++) {
        int b = NBUCKET - 1 - (t * PER + k);
        g_base[b]   = run;
        g_cursor[b] = run;
        run += cnt[k];
    }
}

// ---------------- P3: scatter into bucket segments -----------------------
__global__ void scatter_kernel() {
    uint32_t i = blockIdx.x * blockDim.x + threadIdx.x;
    if (i >= g_count) return;
    unsigned long long key = g_ucand[i];
    uint32_t sb = (uint32_t)(key >> 25);
    uint32_t b  = (sb >> 9) & (NBUCKET - 1);
    uint32_t pos = atomicAdd(&g_cursor[b], 1u);
    g_sorted[pos] = key;
}

// ---------------- P4: sort within each (tiny) bucket ----------------------
__global__ void bucket_sort_kernel() {
    int b = blockIdx.x * blockDim.x + threadIdx.x;
    if (b >= NBUCKET) return;
    uint32_t beg = g_base[b];
    uint32_t n   = g_hist[b];
    for (uint32_t i = 1; i < n; i++) {
        unsigned long long k = g_sorted[beg + i];
        uint32_t j = i;
        while (j > 0 && g_sorted[beg + j - 1] < k) {   // descending
            g_sorted[beg + j] = g_sorted[beg + j - 1];
            j--;
        }
        g_sorted[beg + j] = k;
    }
}

// ---------------- P5: single-block chunked greedy NMS + output ------------
__global__ __launch_bounds__(1024, 1) void nms_kernel(const float* __restrict__ in,
                                                      float* __restrict__ out,
                                                      int out_size) {
    __shared__ float4             s_kept[MAXSEL];
    __shared__ float4             s_cbox[CHUNK];
    __shared__ unsigned long long s_ckey[CHUNK];
    __shared__ uint32_t           s_supp[NWORDS];
    __shared__ uint32_t           s_mask[CHUNK][NWORDS];
    __shared__ int                s_selidx[MAXSEL];
    __shared__ float              s_selscore[MAXSEL];
    __shared__ int                s_selcls[MAXSEL];
    __shared__ int                s_nsel, s_total, s_stop;

    int tid = threadIdx.x;

    // defensively zero the whole output
    for (int i = tid; i < out_size; i += blockDim.x) out[i] = 0.0f;

    if (tid == 0) { s_nsel = 0; s_total = (int)g_count; s_stop = 0; }
    __syncthreads();
    int total = s_total;

    for (int start = 0; start < total; start += CHUNK) {
        if (s_stop) break;                       // uniform: read after last sync
        int m = min(CHUNK, total - start);

        // load chunk keys + gather boxes
        for (int j = tid; j < m; j += blockDim.x) {
            unsigned long long key = g_sorted[start + j];
            s_ckey[j] = key;
            int idx = NBOX - 1 - (int)((key >> 7) & 0x3FFFFu);
            const float* r = in + (size_t)idx * ROWLEN;
            s_cbox[j] = make_float4(r[0], r[1], r[2], r[3]);
        }
        // init suppression bitmap: bits >= m pre-suppressed
        if (tid < NWORDS) {
            uint32_t w = 0;
            int base = tid * 32;
            #pragma unroll
            for (int b2 = 0; b2 < 32; b2++)
                if (base + b2 >= m) w |= (1u << b2);
            s_supp[tid] = w;
        }
        __syncthreads();

        int nk = s_nsel;   // every selection is a kept box
        // (a) suppressed-by-previously-kept, 4 threads per candidate
        {
            int j = tid & (CHUNK - 1);
            int g = tid >> 8;                    // 0..3
            bool sup = false;
            if (j < m) {
                float4 bj = s_cbox[j];
                for (int k = g; k < nk; k += 4) {
                    if (iou_gt(s_kept[k], bj)) { sup = true; break; }
                }
            }
            if (sup) atomicOr(&s_supp[j >> 5], 1u << (j & 31));
        }
        // (b) intra-chunk pairwise mask: thread (j, seg) owns 64 k's
        {
            int j   = tid & (CHUNK - 1);
            int seg = tid >> 8;                  // 0..3
            uint32_t w0 = 0, w1 = 0;
            if (j < m) {
                float4 bj = s_cbox[j];
                int kb = seg * 64;
                for (int kk = 0; kk < 64; kk++) {
                    int k = kb + kk;
                    if (k < m && k != j && iou_gt(bj, s_cbox[k])) {
                        if (kk < 32) w0 |= (1u << kk);
                        else         w1 |= (1u << (kk - 32));
                    }
                }
            }
            s_mask[j][seg * 2]     = w0;
            s_mask[j][seg * 2 + 1] = w1;
        }
        __syncthreads();

        // (c) serial bit-scan (thread 0): exact greedy order
        if (tid == 0) {
            int nsel = s_nsel;
            for (int w = 0; w < NWORDS && nsel < MAXSEL; w++) {
                uint32_t wv = s_supp[w];
                while (wv != 0xFFFFFFFFu) {
                    int b = __ffs(~wv) - 1;
                    int j = w * 32 + b;
                    unsigned long long key = s_ckey[j];
                    int idx = NBOX - 1 - (int)((key >> 7) & 0x3FFFFu);
                    s_selidx[nsel]   = idx;
                    s_selscore[nsel] = __uint_as_float((uint32_t)(key >> 25));
                    s_selcls[nsel]   = (int)(key & 0x7Fu);
                    s_kept[nsel]     = s_cbox[j];
                    nsel++;
                    wv |= (1u << b);
                    wv |= s_mask[j][w];
                    s_supp[w] = wv;
                    for (int w2 = w + 1; w2 < NWORDS; w2++)
                        s_supp[w2] |= s_mask[j][w2];
                    if (nsel >= MAXSEL) break;
                }
            }
            s_nsel = nsel;
            if (nsel >= MAXSEL) s_stop = 1;
        }
        __syncthreads();
    }

    // output: boxes[300*4] | scores[300] | classes[300] | valid[300]
    int nsel = s_nsel;
    for (int t = tid; t < MAXSEL; t += blockDim.x) {
        float4 bx = make_float4(0.f, 0.f, 0.f, 0.f);
        float sc = 0.f, cl = -1.f, va = 0.f;
        if (t < nsel) {
            bx = s_kept[t];
            sc = s_selscore[t];
            cl = (float)s_selcls[t];
            va = 1.f;
        }
        out[t * 4 + 0] = bx.x;
        out[t * 4 + 1] = bx.y;
        out[t * 4 + 2] = bx.z;
        out[t * 4 + 3] = bx.w;
        out[MAXSEL * 4 + t]         = sc;
        out[MAXSEL * 4 + MAXSEL + t]     = cl;
        out[MAXSEL * 4 + MAXSEL * 2 + t] = va;
    }
}

// ---------------- launch ----------------
extern "C" void kernel_launch(void* const* d_in, const int* in_sizes, int n_in,
                              void* d_out, int out_size) {
    const float* in  = (const float*)d_in[0];
    float*       out = (float*)d_out;

    init_kernel<<<(NBUCKET + 255) / 256, 256>>>();
    score_kernel<<<NBOX / 8, 256>>>(in);            // 8 warps/block, warp per box
    scan_kernel<<<1, 1024>>>();
    scatter_kernel<<<NBOX / 256, 256>>>();
    bucket_sort_kernel<<<NBUCKET / 256, 256>>>();
    nms_kernel<<<1, 1024>>>(in, out, out_size);
}